// round 9
// baseline (speedup 1.0000x reference)
#include <cuda_runtime.h>
#include <cstdint>
#include <cmath>
#include <cstring>

#define N_NODES 10000
#define N_EDGES 100000
#define IN1_DIM 288
#define IN2_DIM 9
#define W_DIM   480
#define OUT_DIM 1632

// Per-half slot tables for warp-cooperative stage 1.
// Half 0 (A): instrs {6,9,11,14}, rounds [l2=0 | l2=1 | l2=1 | l2=2]
// Half 1 (B): instrs {0,1,2,3,4,5,7,8,10,12,13}, rounds [l2=0 | l2=1 | l2=2 | l2=2]
struct TPTab2 {
  float cg[2][128][5];
  unsigned short dst[2][128];   // c-buffer element (row*8+k); pads -> dump row
};

// ---------------------------------------------------------------------------
// HOST: exact numpy default_rng(42) replay (validated R7: rel_err 1e-7).
// ---------------------------------------------------------------------------
typedef unsigned __int128 u128_t;
struct HostPcg {
  u128_t st, inc;
  void step() {
    const u128_t M = ((u128_t)2549297995355413924ULL << 64) | 4865540595714422341ULL;
    st = st * M + inc;
  }
  uint64_t n64() {
    step();
    uint64_t hi = (uint64_t)(st >> 64), lo = (uint64_t)st;
    unsigned rot = (unsigned)(st >> 122);
    uint64_t x = hi ^ lo;
    return (x >> rot) | (x << ((64u - rot) & 63u));
  }
  double nd() { return (double)(n64() >> 11) * (1.0 / 9007199254740992.0); }
};

static const int tD1[15] = {1,1,1,3,3,3,3,3,3,5,5,5,5,5,5};
static const int tD2[15] = {1,3,5,1,3,3,3,5,5,1,3,3,5,5,5};
static const int tD3[15] = {1,3,5,3,1,3,5,3,5,5,3,5,1,3,5};

static void build_tab(TPTab2& T) {
  uint32_t pool[4];
  {
    uint32_t hc = 0x43b0d7e5u;  // INIT_A
    auto h = [&hc](uint32_t v) -> uint32_t {
      v ^= hc; hc *= 0x931e8875u; v *= hc; v ^= v >> 16; return v;
    };
    auto mix = [](uint32_t x, uint32_t y) -> uint32_t {
      uint32_t r = (x * 0xca01f9ddu) - (y * 0x4973f715u);  // numpy: subtraction
      r ^= r >> 16;
      return r;
    };
    pool[0] = h(42u); pool[1] = h(0u); pool[2] = h(0u); pool[3] = h(0u);
    for (int s = 0; s < 4; ++s)
      for (int d = 0; d < 4; ++d)
        if (s != d) pool[d] = mix(pool[d], h(pool[s]));
  }
  uint64_t sw[4];
  {
    uint32_t hc = 0x8b51f9ddu;  // INIT_B
    uint32_t w32[8];
    for (int i = 0; i < 8; ++i) {
      uint32_t v = pool[i & 3];
      v ^= hc; hc *= 0x58f38dedu; v *= hc; v ^= v >> 16;
      w32[i] = v;
    }
    for (int k = 0; k < 4; ++k)
      sw[k] = (uint64_t)w32[2 * k] | ((uint64_t)w32[2 * k + 1] << 32);
  }
  HostPcg g;
  {
    u128_t initstate = ((u128_t)sw[0] << 64) | sw[1];
    u128_t initseq   = ((u128_t)sw[2] << 64) | sw[3];
    g.st = 0; g.inc = (initseq << 1) | 1;
    g.step(); g.st += initstate; g.step();
  }

  double zwi[256], zfi[256]; uint64_t zki[256];
  {
    const double m = 4503599627370496.0, r = 3.6541528853610088;
    double f = exp(-0.5 * r * r);
    double v = r * f + sqrt(1.5707963267948966) * erfc(r * 0.7071067811865476);
    double q = v / f, dn = r, tn = r;
    zki[0] = (uint64_t)((dn / q) * m);  zki[1] = 0;
    zwi[0] = q / m;  zwi[255] = dn / m;
    zfi[0] = 1.0;    zfi[255] = f;
    for (int i = 254; i >= 1; --i) {
      dn = sqrt(-2.0 * log(v / dn + exp(-0.5 * dn * dn)));
      zki[i + 1] = (uint64_t)((dn / tn) * m);
      tn = dn;
      zfi[i] = exp(-0.5 * dn * dn);
      zwi[i] = dn / m;
    }
  }
  auto stdnorm = [&]() -> double {
    const double r = 3.6541528853610088, inv_r = 0.27366123732975828;
    for (;;) {
      uint64_t rr = g.n64();
      int idx = (int)(rr & 0xff);
      rr >>= 8;
      int sign = (int)(rr & 1);
      uint64_t rabs = (rr >> 1) & 0x000fffffffffffffULL;
      double x = (double)rabs * zwi[idx];
      if (sign) x = -x;
      if (rabs < zki[idx]) return x;
      if (idx == 0) {
        double xx, yy;
        do {
          xx = -inv_r * log1p(-g.nd());
          yy = -log1p(-g.nd());
        } while (yy + yy <= xx * xx);
        return ((rabs >> 8) & 1) ? -(r + xx) : (r + xx);
      }
      if ((zfi[idx - 1] - zfi[idx]) * g.nd() + zfi[idx] < exp(-0.5 * x * x))
        return x;
    }
  };

  float cgpw[15][125];
  for (int t = 0; t < 15; ++t) {
    int d1 = tD1[t], d2 = tD2[t], d3 = tD3[t], sz = d1 * d2 * d3;
    unsigned char mk[125]; int any = 0;
    for (int q = 0; q < sz; ++q) { mk[q] = (g.nd() < 0.3) ? 1 : 0; any |= mk[q]; }
    if (!any) mk[0] = 1;
    float pw = (float)(1.0 / sqrt((double)(d1 * d2)));
    for (int q = 0; q < sz; ++q) {
      float v = (float)stdnorm();
      cgpw[t][q] = mk[q] ? (v * pw) : 0.0f;
    }
  }

  // --- half definitions: rowbase within each half's c-buffer (dump after last)
  int rbA[15]; for (int i = 0; i < 15; ++i) rbA[i] = -1;
  rbA[6] = 0; rbA[9] = 3; rbA[11] = 8; rbA[14] = 13;        // dump row 18
  int rbB[15]; for (int i = 0; i < 15; ++i) rbB[i] = -1;
  rbB[0] = 0; rbB[1] = 1; rbB[2] = 2; rbB[3] = 3; rbB[4] = 6; rbB[5] = 9;
  rbB[7] = 12; rbB[8] = 15; rbB[10] = 18; rbB[12] = 23; rbB[13] = 28;  // dump 33

  memset(&T, 0, sizeof(T));
  auto fillGroup = [&](int h, const int* rb, const int* grp, int ng, int slot) {
    for (int gi = 0; gi < ng; ++gi) {
      int t = grp[gi], d1 = tD1[t], d2 = tD2[t], d3 = tD3[t];
      for (int i = 0; i < d1; ++i)
        for (int k = 0; k < d3; ++k) {
          for (int j = 0; j < d2; ++j)
            T.cg[h][slot][j] = cgpw[t][(i * d2 + j) * d3 + k];
          T.dst[h][slot] = (unsigned short)((rb[t] + i) * 8 + k);
          ++slot;
        }
    }
  };
  // init all slots to dump row (cg zeros -> writes 0.0 there; benign)
  for (int s = 0; s < 128; ++s) { T.dst[0][s] = 18 * 8; T.dst[1][s] = 33 * 8; }
  // half A: rounds [0:l2=0][32..95:l2=1][96:l2=2]
  { const int g0[1] = {9};      fillGroup(0, rbA, g0, 1, 0);  }   // 25 slots
  { const int g1[2] = {6, 11};  fillGroup(0, rbA, g1, 2, 32); }   // 40 slots
  { const int g2[1] = {14};     fillGroup(0, rbA, g2, 1, 96); }   // 25 slots
  // half B: rounds [0:l2=0][32:l2=1][64..127:l2=2]
  { const int g0[2] = {0, 3};             fillGroup(1, rbB, g0, 2, 0);  }  // 10
  { const int g1[4] = {1, 4, 5, 10};      fillGroup(1, rbB, g1, 4, 32); }  // 30
  { const int g2[5] = {2, 7, 8, 12, 13};  fillGroup(1, rbB, g2, 5, 64); }  // 49
}

// ---------------------------------------------------------------------------
// Device scratch
// ---------------------------------------------------------------------------
__device__ int g_row_ptr[N_NODES + 1];
__device__ int g_cursor[N_NODES];
__device__ int g_edge_ids[N_EDGES];

__global__ void k_zero() {
  int i = blockIdx.x * blockDim.x + threadIdx.x;
  if (i < N_NODES) g_cursor[i] = 0;
}

__global__ void k_hist(const int* __restrict__ dst) {
  int e = blockIdx.x * blockDim.x + threadIdx.x;
  if (e < N_EDGES) atomicAdd(&g_cursor[dst[e]], 1);
}

__global__ void k_scan() {
  __shared__ int s_wsum[32];
  __shared__ int s_carry;
  const int tid = threadIdx.x, lane = tid & 31, w = tid >> 5;
  if (tid == 0) s_carry = 0;
  __syncthreads();
  for (int base = 0; base < N_NODES; base += 1024) {
    int i = base + tid;
    int v = (i < N_NODES) ? g_cursor[i] : 0;
    int x = v;
#pragma unroll
    for (int d = 1; d < 32; d <<= 1) {
      int y = __shfl_up_sync(0xffffffffu, x, d);
      if (lane >= d) x += y;
    }
    if (lane == 31) s_wsum[w] = x;
    __syncthreads();
    if (w == 0) {
      int z = s_wsum[lane];
#pragma unroll
      for (int d = 1; d < 32; d <<= 1) {
        int y = __shfl_up_sync(0xffffffffu, z, d);
        if (lane >= d) z += y;
      }
      s_wsum[lane] = z;
    }
    __syncthreads();
    int warp_excl = (w == 0) ? 0 : s_wsum[w - 1];
    int excl = s_carry + warp_excl + (x - v);
    if (i < N_NODES) { g_row_ptr[i] = excl; g_cursor[i] = 0; }
    __syncthreads();
    if (tid == 0) s_carry += s_wsum[31];
    __syncthreads();
  }
  if (tid == 0) g_row_ptr[N_NODES] = s_carry;
}

__global__ void k_scatter(const int* __restrict__ dst) {
  int e = blockIdx.x * blockDim.x + threadIdx.x;
  if (e < N_EDGES) {
    int d = dst[e];
    int pos = atomicAdd(&g_cursor[d], 1);
    g_edge_ids[g_row_ptr[d] + pos] = e;
  }
}

// ---------------------------------------------------------------------------
// Main kernel: 2 warps per node (instruction halves), lane = mul u.
// ---------------------------------------------------------------------------
#define S2_1(AB, RB, KB, WI, DD) { float t0 = 0.f;                             \
  _Pragma("unroll") for (int i = 0; i < (DD); ++i)                             \
    t0 = fmaf(a[(AB) + i], cw[((RB) + i) * 8], t0);                            \
  acc[(KB)] = fmaf(wv[(WI)], t0, acc[(KB)]); }

#define S2_3(AB, RB, KB, WI, DD) { float t0 = 0.f, t1 = 0.f, t2 = 0.f;         \
  _Pragma("unroll") for (int i = 0; i < (DD); ++i) {                           \
    float4 cv = *(const float4*)&cw[((RB) + i) * 8];                           \
    float ai = a[(AB) + i];                                                    \
    t0 = fmaf(ai, cv.x, t0); t1 = fmaf(ai, cv.y, t1); t2 = fmaf(ai, cv.z, t2); } \
  acc[(KB)]     = fmaf(wv[(WI)], t0, acc[(KB)]);                               \
  acc[(KB) + 1] = fmaf(wv[(WI)], t1, acc[(KB) + 1]);                           \
  acc[(KB) + 2] = fmaf(wv[(WI)], t2, acc[(KB) + 2]); }

#define S2_5(AB, RB, KB, WI, DD) {                                             \
  float t0 = 0.f, t1 = 0.f, t2 = 0.f, t3 = 0.f, t4 = 0.f;                      \
  _Pragma("unroll") for (int i = 0; i < (DD); ++i) {                           \
    float4 cv = *(const float4*)&cw[((RB) + i) * 8];                           \
    float c4 = cw[((RB) + i) * 8 + 4];                                         \
    float ai = a[(AB) + i];                                                    \
    t0 = fmaf(ai, cv.x, t0); t1 = fmaf(ai, cv.y, t1); t2 = fmaf(ai, cv.z, t2); \
    t3 = fmaf(ai, cv.w, t3); t4 = fmaf(ai, c4, t4); }                          \
  acc[(KB)]     = fmaf(wv[(WI)], t0, acc[(KB)]);                               \
  acc[(KB) + 1] = fmaf(wv[(WI)], t1, acc[(KB) + 1]);                           \
  acc[(KB) + 2] = fmaf(wv[(WI)], t2, acc[(KB) + 2]);                           \
  acc[(KB) + 3] = fmaf(wv[(WI)], t3, acc[(KB) + 3]);                           \
  acc[(KB) + 4] = fmaf(wv[(WI)], t4, acc[(KB) + 4]); }

#define STO(OFF, DD, KB)                                                       \
  _Pragma("unroll") for (int k = 0; k < (DD); ++k)                             \
    O[(OFF) + lane * (DD) + k] = acc[(KB) + k];

__global__ void __launch_bounds__(128)
k_tp(const TPTab2 tab,
     const float* __restrict__ in1, const float* __restrict__ in2,
     const float* __restrict__ wt, const int* __restrict__ src,
     float* __restrict__ out)
{
  __shared__ __align__(16) float s_c[4][272];
  const int wid = threadIdx.x >> 5;
  const int lane = threadIdx.x & 31;
  const int node = blockIdx.x * 2 + (wid >> 1);
  const int half = wid & 1;
  float* cw = s_c[wid];

  // hoist this lane's stage-1 cg + destinations (4 rounds)
  const float c0  = tab.cg[half][lane][0];
  const int   d0  = tab.dst[half][lane];
  const float c1a = tab.cg[half][32 + lane][0], c1b = tab.cg[half][32 + lane][1],
              c1c = tab.cg[half][32 + lane][2];
  const int   d1_ = tab.dst[half][32 + lane];
  // round 2: half A uses 3 coeffs (l2=1), half B uses 5 (l2=2)
  const float c2a = tab.cg[half][64 + lane][0], c2b = tab.cg[half][64 + lane][1],
              c2c = tab.cg[half][64 + lane][2], c2d = tab.cg[half][64 + lane][3],
              c2e = tab.cg[half][64 + lane][4];
  const int   d2_ = tab.dst[half][64 + lane];
  const float c3a = tab.cg[half][96 + lane][0], c3b = tab.cg[half][96 + lane][1],
              c3c = tab.cg[half][96 + lane][2], c3d = tab.cg[half][96 + lane][3],
              c3e = tab.cg[half][96 + lane][4];
  const int   d3_ = tab.dst[half][96 + lane];

  float acc[31];
#pragma unroll
  for (int k = 0; k < 31; ++k) acc[k] = 0.f;

  const int beg = g_row_ptr[node];
  const int end = g_row_ptr[node + 1];

  int e = 0, sN = 0;
  if (beg < end) { e = g_edge_ids[beg]; sN = src[e]; }

  for (int t = beg; t < end; ++t) {
    const float* A = in1 + (size_t)sN * IN1_DIM;
    float a[9];
    a[0] = A[lane];
    { const float* p = A + 32 + lane * 3;  a[1] = p[0]; a[2] = p[1]; a[3] = p[2]; }
    { const float* p = A + 128 + lane * 5; a[4] = p[0]; a[5] = p[1]; a[6] = p[2]; a[7] = p[3]; a[8] = p[4]; }

    float b[9];
    { const float* B = in2 + (size_t)e * IN2_DIM;
#pragma unroll
      for (int j = 0; j < 9; ++j) b[j] = B[j]; }

    float wv[11];
    { const float* W = wt + (size_t)e * W_DIM + lane;
      if (half == 0) {
        wv[0] = W[6 * 32]; wv[1] = W[9 * 32]; wv[2] = W[11 * 32]; wv[3] = W[14 * 32];
      } else {
        wv[0] = W[0];       wv[1] = W[32];      wv[2] = W[64];      wv[3] = W[96];
        wv[4] = W[128];     wv[5] = W[160];     wv[6] = W[224];     wv[7] = W[256];
        wv[8] = W[320];     wv[9] = W[384];     wv[10] = W[416];
      }
    }

    // prefetch next edge id + src row (removes 2 serial latencies per edge)
    if (t + 1 < end) { e = g_edge_ids[t + 1]; sN = src[e]; }

    __syncwarp();  // prior stage-2 reads complete before overwriting cw
    cw[d0]  = c0 * b[0];
    cw[d1_] = fmaf(c1c, b[3], fmaf(c1b, b[2], c1a * b[1]));
    if (half == 0) {
      cw[d2_] = fmaf(c2c, b[3], fmaf(c2b, b[2], c2a * b[1]));                   // l2=1
    } else {
      cw[d2_] = fmaf(c2e, b[8], fmaf(c2d, b[7], fmaf(c2c, b[6], fmaf(c2b, b[5], c2a * b[4]))));  // l2=2
    }
    cw[d3_] = fmaf(c3e, b[8], fmaf(c3d, b[7], fmaf(c3c, b[6], fmaf(c3b, b[5], c3a * b[4]))));
    __syncwarp();

    if (half == 0) {
      S2_5(1, 0, 0, 0, 3);     // instr6
      S2_5(4, 3, 5, 1, 5);     // instr9
      S2_5(4, 8, 10, 2, 5);    // instr11
      S2_5(4, 13, 15, 3, 5);   // instr14
    } else {
      S2_1(0, 0, 0, 0, 1);     // instr0
      S2_3(0, 1, 1, 1, 1);     // instr1
      S2_5(0, 2, 4, 2, 1);     // instr2
      S2_3(1, 3, 9, 3, 3);     // instr3
      S2_1(1, 6, 12, 4, 3);    // instr4
      S2_3(1, 9, 13, 5, 3);    // instr5
      S2_3(1, 12, 16, 6, 3);   // instr7
      S2_5(1, 15, 19, 7, 3);   // instr8
      S2_3(4, 18, 24, 8, 5);   // instr10
      S2_1(4, 23, 27, 9, 5);   // instr12
      S2_3(4, 28, 28, 10, 5);  // instr13
    }
  }

  float* O = out + (size_t)node * OUT_DIM;
  if (half == 0) {
    STO(512, 5, 0);    // instr6
    STO(928, 5, 5);    // instr9
    STO(1184, 5, 10);  // instr11
    STO(1472, 5, 15);  // instr14
  } else {
    STO(0, 1, 0);      // instr0
    STO(32, 3, 1);     // instr1
    STO(128, 5, 4);    // instr2
    STO(288, 3, 9);    // instr3
    STO(384, 1, 12);   // instr4
    STO(416, 3, 13);   // instr5
    STO(672, 3, 16);   // instr7
    STO(768, 5, 19);   // instr8
    STO(1088, 3, 24);  // instr10
    STO(1344, 1, 27);  // instr12
    STO(1376, 3, 28);  // instr13
  }
}

// ---------------------------------------------------------------------------
// Launch
// ---------------------------------------------------------------------------
extern "C" void kernel_launch(void* const* d_in, const int* in_sizes, int n_in,
                              void* d_out, int out_size) {
  const float* in1 = (const float*)d_in[0];
  const float* in2 = (const float*)d_in[1];
  const float* wt = (const float*)d_in[2];
  const int* src = (const int*)d_in[3];
  const int* dst = (const int*)d_in[4];
  float* out = (float*)d_out;

  TPTab2 tab;
  build_tab(tab);

  k_zero<<<(N_NODES + 255) / 256, 256>>>();
  k_hist<<<(N_EDGES + 255) / 256, 256>>>(dst);
  k_scan<<<1, 1024>>>();
  k_scatter<<<(N_EDGES + 255) / 256, 256>>>(dst);
  k_tp<<<N_NODES / 2, 128>>>(tab, in1, in2, wt, src, out);  // 2 warps/node
}

// round 11
// speedup vs baseline: 1.0984x; 1.0984x over previous
#include <cuda_runtime.h>
#include <cstdint>
#include <cmath>
#include <cstring>

#define N_NODES 10000
#define N_EDGES 100000
#define IN1_DIM 288
#define IN2_DIM 9
#define W_DIM   480
#define OUT_DIM 1632

// slot tables for the warp-cooperative stage 1 (validated in R7: rel_err 1.1e-7)
struct TPTab {
  float cgs[256][5];          // per-slot padded cg row (j entries, path_w folded)
  unsigned short dst[256];    // slot -> c-buffer element index (row*8+k); 408 = dump
};

// ---------------------------------------------------------------------------
// HOST: exact numpy default_rng(42) replay (validated R7).
// ---------------------------------------------------------------------------
typedef unsigned __int128 u128_t;
struct HostPcg {
  u128_t st, inc;
  void step() {
    const u128_t M = ((u128_t)2549297995355413924ULL << 64) | 4865540595714422341ULL;
    st = st * M + inc;
  }
  uint64_t n64() {
    step();
    uint64_t hi = (uint64_t)(st >> 64), lo = (uint64_t)st;
    unsigned rot = (unsigned)(st >> 122);
    uint64_t x = hi ^ lo;
    return (x >> rot) | (x << ((64u - rot) & 63u));
  }
  double nd() { return (double)(n64() >> 11) * (1.0 / 9007199254740992.0); }
};

static const int tD1[15] = {1,1,1,3,3,3,3,3,3,5,5,5,5,5,5};
static const int tD2[15] = {1,3,5,1,3,3,3,5,5,1,3,3,5,5,5};
static const int tD3[15] = {1,3,5,3,1,3,5,3,5,5,3,5,1,3,5};
static const int tROWB[15] = {0,1,2,3,6,9,12,15,18,21,26,31,36,41,46};

static void build_tab(TPTab& T) {
  uint32_t pool[4];
  {
    uint32_t hc = 0x43b0d7e5u;  // INIT_A
    auto h = [&hc](uint32_t v) -> uint32_t {
      v ^= hc; hc *= 0x931e8875u; v *= hc; v ^= v >> 16; return v;
    };
    auto mix = [](uint32_t x, uint32_t y) -> uint32_t {
      uint32_t r = (x * 0xca01f9ddu) - (y * 0x4973f715u);  // numpy: subtraction
      r ^= r >> 16;
      return r;
    };
    pool[0] = h(42u); pool[1] = h(0u); pool[2] = h(0u); pool[3] = h(0u);
    for (int s = 0; s < 4; ++s)
      for (int d = 0; d < 4; ++d)
        if (s != d) pool[d] = mix(pool[d], h(pool[s]));
  }
  uint64_t sw[4];
  {
    uint32_t hc = 0x8b51f9ddu;  // INIT_B
    uint32_t w32[8];
    for (int i = 0; i < 8; ++i) {
      uint32_t v = pool[i & 3];
      v ^= hc; hc *= 0x58f38dedu; v *= hc; v ^= v >> 16;
      w32[i] = v;
    }
    for (int k = 0; k < 4; ++k)
      sw[k] = (uint64_t)w32[2 * k] | ((uint64_t)w32[2 * k + 1] << 32);
  }
  HostPcg g;
  {
    u128_t initstate = ((u128_t)sw[0] << 64) | sw[1];
    u128_t initseq   = ((u128_t)sw[2] << 64) | sw[3];
    g.st = 0; g.inc = (initseq << 1) | 1;
    g.step(); g.st += initstate; g.step();
  }

  double zwi[256], zfi[256]; uint64_t zki[256];
  {
    const double m = 4503599627370496.0, r = 3.6541528853610088;
    double f = exp(-0.5 * r * r);
    double v = r * f + sqrt(1.5707963267948966) * erfc(r * 0.7071067811865476);
    double q = v / f, dn = r, tn = r;
    zki[0] = (uint64_t)((dn / q) * m);  zki[1] = 0;
    zwi[0] = q / m;  zwi[255] = dn / m;
    zfi[0] = 1.0;    zfi[255] = f;
    for (int i = 254; i >= 1; --i) {
      dn = sqrt(-2.0 * log(v / dn + exp(-0.5 * dn * dn)));
      zki[i + 1] = (uint64_t)((dn / tn) * m);
      tn = dn;
      zfi[i] = exp(-0.5 * dn * dn);
      zwi[i] = dn / m;
    }
  }
  auto stdnorm = [&]() -> double {
    const double r = 3.6541528853610088, inv_r = 0.27366123732975828;
    for (;;) {
      uint64_t rr = g.n64();
      int idx = (int)(rr & 0xff);
      rr >>= 8;
      int sign = (int)(rr & 1);
      uint64_t rabs = (rr >> 1) & 0x000fffffffffffffULL;
      double x = (double)rabs * zwi[idx];
      if (sign) x = -x;
      if (rabs < zki[idx]) return x;
      if (idx == 0) {
        double xx, yy;
        do {
          xx = -inv_r * log1p(-g.nd());
          yy = -log1p(-g.nd());
        } while (yy + yy <= xx * xx);
        return ((rabs >> 8) & 1) ? -(r + xx) : (r + xx);
      }
      if ((zfi[idx - 1] - zfi[idx]) * g.nd() + zfi[idx] < exp(-0.5 * x * x))
        return x;
    }
  };

  float cgpw[15][125];
  for (int t = 0; t < 15; ++t) {
    int d1 = tD1[t], d2 = tD2[t], d3 = tD3[t], sz = d1 * d2 * d3;
    unsigned char mk[125]; int any = 0;
    for (int q = 0; q < sz; ++q) { mk[q] = (g.nd() < 0.3) ? 1 : 0; any |= mk[q]; }
    if (!any) mk[0] = 1;
    float pw = (float)(1.0 / sqrt((double)(d1 * d2)));
    for (int q = 0; q < sz; ++q) {
      float v = (float)stdnorm();
      cgpw[t][q] = mk[q] ? (v * pw) : 0.0f;
    }
  }

  memset(&T, 0, sizeof(T));
  for (int s = 0; s < 256; ++s) T.dst[s] = 408;  // dump element
  const int gA[3] = {0, 3, 9};                 // l2=0  -> slots [0,64)
  const int gB[6] = {1, 4, 5, 6, 10, 11};      // l2=1  -> slots [64,160)
  const int gC[6] = {2, 7, 8, 12, 13, 14};     // l2=2  -> slots [160,256)
  auto fill = [&](const int* grp, int ng, int slot) {
    for (int gi = 0; gi < ng; ++gi) {
      int t = grp[gi], d1 = tD1[t], d2 = tD2[t], d3 = tD3[t];
      for (int i = 0; i < d1; ++i)
        for (int k = 0; k < d3; ++k) {
          for (int j = 0; j < d2; ++j)
            T.cgs[slot][j] = cgpw[t][(i * d2 + j) * d3 + k];
          T.dst[slot] = (unsigned short)((tROWB[t] + i) * 8 + k);
          ++slot;
        }
    }
  };
  fill(gA, 3, 0); fill(gB, 6, 64); fill(gC, 6, 160);
}

// ---------------------------------------------------------------------------
// Device scratch
// ---------------------------------------------------------------------------
__device__ int g_row_ptr[N_NODES + 1];
__device__ int g_cursor[N_NODES];
__device__ int g_edge_ids[N_EDGES];

__global__ void k_zero() {
  int i = blockIdx.x * blockDim.x + threadIdx.x;
  if (i < N_NODES) g_cursor[i] = 0;
}

__global__ void k_hist(const int* __restrict__ dst) {
  int e = blockIdx.x * blockDim.x + threadIdx.x;
  if (e < N_EDGES) atomicAdd(&g_cursor[dst[e]], 1);
}

__global__ void k_scan() {
  __shared__ int s_wsum[32];
  __shared__ int s_carry;
  const int tid = threadIdx.x, lane = tid & 31, w = tid >> 5;
  if (tid == 0) s_carry = 0;
  __syncthreads();
  for (int base = 0; base < N_NODES; base += 1024) {
    int i = base + tid;
    int v = (i < N_NODES) ? g_cursor[i] : 0;
    int x = v;
#pragma unroll
    for (int d = 1; d < 32; d <<= 1) {
      int y = __shfl_up_sync(0xffffffffu, x, d);
      if (lane >= d) x += y;
    }
    if (lane == 31) s_wsum[w] = x;
    __syncthreads();
    if (w == 0) {
      int z = s_wsum[lane];
#pragma unroll
      for (int d = 1; d < 32; d <<= 1) {
        int y = __shfl_up_sync(0xffffffffu, z, d);
        if (lane >= d) z += y;
      }
      s_wsum[lane] = z;
    }
    __syncthreads();
    int warp_excl = (w == 0) ? 0 : s_wsum[w - 1];
    int excl = s_carry + warp_excl + (x - v);
    if (i < N_NODES) { g_row_ptr[i] = excl; g_cursor[i] = 0; }
    __syncthreads();
    if (tid == 0) s_carry += s_wsum[31];
    __syncthreads();
  }
  if (tid == 0) g_row_ptr[N_NODES] = s_carry;
}

__global__ void k_scatter(const int* __restrict__ dst) {
  int e = blockIdx.x * blockDim.x + threadIdx.x;
  if (e < N_EDGES) {
    int d = dst[e];
    int pos = atomicAdd(&g_cursor[d], 1);
    g_edge_ids[g_row_ptr[d] + pos] = e;
  }
}

// ---------------------------------------------------------------------------
// Main kernel: warp per node, 2-stage software pipeline over a/b/w payload.
// ---------------------------------------------------------------------------
#define S2_1(AB, RB, KB, WI, DD, AA, WW) { float t0 = 0.f;                     \
  _Pragma("unroll") for (int i = 0; i < (DD); ++i)                             \
    t0 = fmaf(AA[(AB) + i], cw[((RB) + i) * 8], t0);                           \
  acc[(KB)] = fmaf(WW[(WI)], t0, acc[(KB)]); }

#define S2_3(AB, RB, KB, WI, DD, AA, WW) { float t0 = 0.f, t1 = 0.f, t2 = 0.f; \
  _Pragma("unroll") for (int i = 0; i < (DD); ++i) {                           \
    float4 cv = *(const float4*)&cw[((RB) + i) * 8];                           \
    float ai = AA[(AB) + i];                                                   \
    t0 = fmaf(ai, cv.x, t0); t1 = fmaf(ai, cv.y, t1); t2 = fmaf(ai, cv.z, t2); } \
  acc[(KB)]     = fmaf(WW[(WI)], t0, acc[(KB)]);                               \
  acc[(KB) + 1] = fmaf(WW[(WI)], t1, acc[(KB) + 1]);                           \
  acc[(KB) + 2] = fmaf(WW[(WI)], t2, acc[(KB) + 2]); }

#define S2_5(AB, RB, KB, WI, DD, AA, WW) {                                     \
  float t0 = 0.f, t1 = 0.f, t2 = 0.f, t3 = 0.f, t4 = 0.f;                      \
  _Pragma("unroll") for (int i = 0; i < (DD); ++i) {                           \
    float4 cv = *(const float4*)&cw[((RB) + i) * 8];                           \
    float c4 = cw[((RB) + i) * 8 + 4];                                         \
    float ai = AA[(AB) + i];                                                   \
    t0 = fmaf(ai, cv.x, t0); t1 = fmaf(ai, cv.y, t1); t2 = fmaf(ai, cv.z, t2); \
    t3 = fmaf(ai, cv.w, t3); t4 = fmaf(ai, c4, t4); }                          \
  acc[(KB)]     = fmaf(WW[(WI)], t0, acc[(KB)]);                               \
  acc[(KB) + 1] = fmaf(WW[(WI)], t1, acc[(KB) + 1]);                           \
  acc[(KB) + 2] = fmaf(WW[(WI)], t2, acc[(KB) + 2]);                           \
  acc[(KB) + 3] = fmaf(WW[(WI)], t3, acc[(KB) + 3]);                           \
  acc[(KB) + 4] = fmaf(WW[(WI)], t4, acc[(KB) + 4]); }

#define STO(OFF, DD, KB)                                                       \
  _Pragma("unroll") for (int k = 0; k < (DD); ++k)                             \
    O[(OFF) + lane * (DD) + k] = acc[(KB) + k];

#define LOAD_A(AA, S)                                                          \
  { const float* A_ = in1 + (size_t)(S) * IN1_DIM;                             \
    AA[0] = A_[lane];                                                          \
    { const float* p = A_ + 32 + lane * 3;  AA[1] = p[0]; AA[2] = p[1]; AA[3] = p[2]; } \
    { const float* p = A_ + 128 + lane * 5; AA[4] = p[0]; AA[5] = p[1]; AA[6] = p[2]; AA[7] = p[3]; AA[8] = p[4]; } }

#define LOAD_B(BB, E)                                                          \
  { const float* B_ = in2 + (size_t)(E) * IN2_DIM;                             \
    _Pragma("unroll") for (int j = 0; j < 9; ++j) BB[j] = B_[j]; }

#define LOAD_W(WW, E)                                                          \
  { const float* W_ = wt + (size_t)(E) * W_DIM + lane;                         \
    _Pragma("unroll") for (int q = 0; q < 15; ++q) WW[q] = W_[q * 32]; }

// One pipelined edge iteration: compute with CUR bufs, load NXT bufs (edge eA/sA),
// then advance eA/sA to t+2.
#define EDGE_BODY(aC, bC, wC, aN, bN, wN)                                      \
  {                                                                            \
    const bool hasN = (t + 1 < end);                                           \
    /* issue next-edge a loads early (deepest latency, L2 gather) */           \
    if (hasN) { LOAD_A(aN, sA); }                                              \
    /* stage 1 with current b (b regs die here) */                             \
    __syncwarp();                                                              \
    cw[d0]  = A0c0 * bC[0];                                                    \
    cw[d1_] = A1c0 * bC[0];                                                    \
    cw[d2_] = fmaf(B0c2, bC[3], fmaf(B0c1, bC[2], B0c0 * bC[1]));              \
    cw[d3_] = fmaf(B1c2, bC[3], fmaf(B1c1, bC[2], B1c0 * bC[1]));              \
    cw[d4_] = fmaf(B2c2, bC[3], fmaf(B2c1, bC[2], B2c0 * bC[1]));              \
    cw[d5_] = fmaf(C0c4, bC[8], fmaf(C0c3, bC[7], fmaf(C0c2, bC[6], fmaf(C0c1, bC[5], C0c0 * bC[4])))); \
    cw[d6_] = fmaf(C1c4, bC[8], fmaf(C1c3, bC[7], fmaf(C1c2, bC[6], fmaf(C1c1, bC[5], C1c0 * bC[4])))); \
    cw[d7_] = fmaf(C2c4, bC[8], fmaf(C2c3, bC[7], fmaf(C2c2, bC[6], fmaf(C2c1, bC[5], C2c0 * bC[4])))); \
    __syncwarp();                                                              \
    /* next-edge b + w loads (land during stage 2) */                          \
    if (hasN) { LOAD_B(bN, eA); LOAD_W(wN, eA); }                              \
    /* advance lookahead to t+2 */                                             \
    if (t + 2 < end) { eA = g_edge_ids[t + 2]; sA = src[eA]; }                 \
    /* stage 2 */                                                              \
    S2_1(0, 0, 0, 0, 1, aC, wC);                                               \
    S2_3(0, 1, 1, 1, 1, aC, wC);                                               \
    S2_5(0, 2, 4, 2, 1, aC, wC);                                               \
    S2_3(1, 3, 9, 3, 3, aC, wC);                                               \
    S2_1(1, 6, 12, 4, 3, aC, wC);                                              \
    S2_3(1, 9, 13, 5, 3, aC, wC);                                              \
    S2_5(1, 12, 16, 6, 3, aC, wC);                                             \
    S2_3(1, 15, 21, 7, 3, aC, wC);                                             \
    S2_5(1, 18, 24, 8, 3, aC, wC);                                             \
    S2_5(4, 21, 29, 9, 5, aC, wC);                                             \
    S2_3(4, 26, 34, 10, 5, aC, wC);                                            \
    S2_5(4, 31, 37, 11, 5, aC, wC);                                            \
    S2_1(4, 36, 42, 12, 5, aC, wC);                                            \
    S2_3(4, 41, 43, 13, 5, aC, wC);                                            \
    S2_5(4, 46, 46, 14, 5, aC, wC);                                            \
  }

__global__ void __launch_bounds__(128, 3)
k_tp(const TPTab tab,
     const float* __restrict__ in1, const float* __restrict__ in2,
     const float* __restrict__ wt, const int* __restrict__ src,
     float* __restrict__ out)
{
  __shared__ __align__(16) float s_c[4][416];
  const int w = threadIdx.x >> 5;
  const int lane = threadIdx.x & 31;
  const int node = blockIdx.x * 4 + w;
  if (node >= N_NODES) return;
  float* cw = s_c[w];

  // hoist this lane's stage-1 cg + destinations (validated R7 layout)
  const float A0c0 = tab.cgs[lane][0];
  const float A1c0 = tab.cgs[32 + lane][0];
  const float B0c0 = tab.cgs[64 + lane][0],  B0c1 = tab.cgs[64 + lane][1],  B0c2 = tab.cgs[64 + lane][2];
  const float B1c0 = tab.cgs[96 + lane][0],  B1c1 = tab.cgs[96 + lane][1],  B1c2 = tab.cgs[96 + lane][2];
  const float B2c0 = tab.cgs[128 + lane][0], B2c1 = tab.cgs[128 + lane][1], B2c2 = tab.cgs[128 + lane][2];
  const float C0c0 = tab.cgs[160 + lane][0], C0c1 = tab.cgs[160 + lane][1], C0c2 = tab.cgs[160 + lane][2],
              C0c3 = tab.cgs[160 + lane][3], C0c4 = tab.cgs[160 + lane][4];
  const float C1c0 = tab.cgs[192 + lane][0], C1c1 = tab.cgs[192 + lane][1], C1c2 = tab.cgs[192 + lane][2],
              C1c3 = tab.cgs[192 + lane][3], C1c4 = tab.cgs[192 + lane][4];
  const float C2c0 = tab.cgs[224 + lane][0], C2c1 = tab.cgs[224 + lane][1], C2c2 = tab.cgs[224 + lane][2],
              C2c3 = tab.cgs[224 + lane][3], C2c4 = tab.cgs[224 + lane][4];
  const int d0  = tab.dst[lane],        d1_ = tab.dst[32 + lane];
  const int d2_ = tab.dst[64 + lane],   d3_ = tab.dst[96 + lane];
  const int d4_ = tab.dst[128 + lane],  d5_ = tab.dst[160 + lane];
  const int d6_ = tab.dst[192 + lane],  d7_ = tab.dst[224 + lane];

  float acc[51];
#pragma unroll
  for (int k = 0; k < 51; ++k) acc[k] = 0.f;

  const int beg = g_row_ptr[node];
  const int end = g_row_ptr[node + 1];

  float a0[9], b0[9], w0[15], a1[9], b1[9], w1[15];
  int eA = 0, sA = 0;

  if (beg < end) {
    int eC = g_edge_ids[beg];
    int sC = src[eC];
    LOAD_A(a0, sC); LOAD_B(b0, eC); LOAD_W(w0, eC);
    if (beg + 1 < end) { eA = g_edge_ids[beg + 1]; sA = src[eA]; }
  }

  int t = beg;
  while (t < end) {
    EDGE_BODY(a0, b0, w0, a1, b1, w1);
    ++t; if (t >= end) break;
    EDGE_BODY(a1, b1, w1, a0, b0, w0);
    ++t;
  }

  float* O = out + (size_t)node * OUT_DIM;
  STO(0, 1, 0);
  STO(32, 3, 1);
  STO(128, 5, 4);
  STO(288, 3, 9);
  STO(384, 1, 12);
  STO(416, 3, 13);
  STO(512, 5, 16);
  STO(672, 3, 21);
  STO(768, 5, 24);
  STO(928, 5, 29);
  STO(1088, 3, 34);
  STO(1184, 5, 37);
  STO(1344, 1, 42);
  STO(1376, 3, 43);
  STO(1472, 5, 46);
}

// ---------------------------------------------------------------------------
// Launch
// ---------------------------------------------------------------------------
extern "C" void kernel_launch(void* const* d_in, const int* in_sizes, int n_in,
                              void* d_out, int out_size) {
  const float* in1 = (const float*)d_in[0];
  const float* in2 = (const float*)d_in[1];
  const float* wt = (const float*)d_in[2];
  const int* src = (const int*)d_in[3];
  const int* dst = (const int*)d_in[4];
  float* out = (float*)d_out;

  TPTab tab;
  build_tab(tab);

  k_zero<<<(N_NODES + 255) / 256, 256>>>();
  k_hist<<<(N_EDGES + 255) / 256, 256>>>(dst);
  k_scan<<<1, 1024>>>();
  k_scatter<<<(N_EDGES + 255) / 256, 256>>>(dst);
  k_tp<<<(N_NODES + 3) / 4, 128>>>(tab, in1, in2, wt, src, out);
}